// round 3
// baseline (speedup 1.0000x reference)
#include <cuda_runtime.h>
#include <math.h>

// Problem constants
#define NUM_EMBED   512
#define EMBED_DIM   64
#define BATCH       4
#define SPATIAL     32768           // 32*32*32
#define N_TOKENS    (BATCH*SPATIAL) // 131072
#define Q_ELEMS     (BATCH*EMBED_DIM*SPATIAL) // 8388608

// Output offsets (tuple flattened, float32)
#define OFF_LOSS      0
#define OFF_Q         1
#define OFF_PERP      (OFF_Q + Q_ELEMS)                 // 8388609
#define OFF_IDX       (OFF_PERP + 1)                    // 8388610
#define OFF_NEWEMBED  (OFF_IDX + N_TOKENS)              // 8519682
#define OFF_CS        (OFF_NEWEMBED + NUM_EMBED*EMBED_DIM) // 8552450
#define OFF_EA        (OFF_CS + NUM_EMBED)              // 8552962

#define DECAY           0.99f
#define ONE_MINUS_DECAY 0.01f
#define COMMIT_COST     0.25f
#define LAPLACE_ALPHA   1e-5f

// Scratch (device globals — no allocations allowed)
__device__ float  g_counts[NUM_EMBED];
__device__ float  g_dw[NUM_EMBED * EMBED_DIM];
__device__ double g_loss;

// ---------------------------------------------------------------------------
// Kernel 0: zero scratch (graph replays require re-zeroing every launch)
// ---------------------------------------------------------------------------
__global__ void vq_zero_kernel() {
    int i = blockIdx.x * blockDim.x + threadIdx.x;
    if (i < NUM_EMBED * EMBED_DIM) g_dw[i] = 0.0f;
    if (i < NUM_EMBED)             g_counts[i] = 0.0f;
    if (i == 0)                    g_loss = 0.0;
}

// ---------------------------------------------------------------------------
// Kernel 1: fused distance/argmin + quantized write + stats + loss partial
// Grid: 512 CTAs x 256 threads, 1 token per thread.
// smem: negated embed [512][64] + half-norms [512]  = 133120 B
// ---------------------------------------------------------------------------
#define MAIN_THREADS 256
#define MAIN_CTAS    (N_TOKENS / MAIN_THREADS)   // 512
#define SMEM_BYTES   ((NUM_EMBED * EMBED_DIM + NUM_EMBED) * 4)

extern __shared__ float smem_dyn[];

__global__ void __launch_bounds__(MAIN_THREADS, 1)
vq_main_kernel(const float* __restrict__ inputs,
               const float* __restrict__ embed,
               float* __restrict__ out)
{
    float* ne    = smem_dyn;                          // -embed, [k*64 + c]
    float* halfn = smem_dyn + NUM_EMBED * EMBED_DIM;  // 0.5*||e_k||^2

    // Load negated embed into shared
    for (int i = threadIdx.x; i < NUM_EMBED * EMBED_DIM; i += blockDim.x)
        ne[i] = -embed[i];
    __syncthreads();
    // Half norms (sequential c order)
    for (int k = threadIdx.x; k < NUM_EMBED; k += blockDim.x) {
        const float* row = ne + k * EMBED_DIM;
        float s = 0.0f;
        #pragma unroll
        for (int c = 0; c < EMBED_DIM; c++) s = fmaf(row[c], row[c], s);
        halfn[k] = 0.5f * s;
    }
    __syncthreads();

    // Token for this thread
    const int n = blockIdx.x * MAIN_THREADS + threadIdx.x;  // coalesced in s
    const int b = n >> 15;          // / SPATIAL
    const int s = n & (SPATIAL - 1);
    const float* xin = inputs + (size_t)b * (EMBED_DIM * SPATIAL) + s;

    // Load x[64] into registers (coalesced per channel across the warp)
    float4 x4[EMBED_DIM / 4];
    #pragma unroll
    for (int c4 = 0; c4 < EMBED_DIM / 4; c4++) {
        x4[c4].x = xin[(size_t)(4 * c4 + 0) * SPATIAL];
        x4[c4].y = xin[(size_t)(4 * c4 + 1) * SPATIAL];
        x4[c4].z = xin[(size_t)(4 * c4 + 2) * SPATIAL];
        x4[c4].w = xin[(size_t)(4 * c4 + 3) * SPATIAL];
    }

    // Argmin over codes: h_k = 0.5||e_k||^2 - x . e_k  (ne holds -e)
    float best = 3.402823466e38f;
    int bestk = 0;
    #pragma unroll 1
    for (int k = 0; k < NUM_EMBED; k += 4) {
        const float4* __restrict__ r0 = reinterpret_cast<const float4*>(ne + (size_t)(k + 0) * EMBED_DIM);
        const float4* __restrict__ r1 = reinterpret_cast<const float4*>(ne + (size_t)(k + 1) * EMBED_DIM);
        const float4* __restrict__ r2 = reinterpret_cast<const float4*>(ne + (size_t)(k + 2) * EMBED_DIM);
        const float4* __restrict__ r3 = reinterpret_cast<const float4*>(ne + (size_t)(k + 3) * EMBED_DIM);
        float a0 = halfn[k + 0];
        float a1 = halfn[k + 1];
        float a2 = halfn[k + 2];
        float a3 = halfn[k + 3];
        #pragma unroll
        for (int c4 = 0; c4 < EMBED_DIM / 4; c4++) {
            const float4 xv = x4[c4];
            const float4 v0 = r0[c4];
            const float4 v1 = r1[c4];
            const float4 v2 = r2[c4];
            const float4 v3 = r3[c4];
            a0 = fmaf(xv.x, v0.x, a0); a0 = fmaf(xv.y, v0.y, a0);
            a0 = fmaf(xv.z, v0.z, a0); a0 = fmaf(xv.w, v0.w, a0);
            a1 = fmaf(xv.x, v1.x, a1); a1 = fmaf(xv.y, v1.y, a1);
            a1 = fmaf(xv.z, v1.z, a1); a1 = fmaf(xv.w, v1.w, a1);
            a2 = fmaf(xv.x, v2.x, a2); a2 = fmaf(xv.y, v2.y, a2);
            a2 = fmaf(xv.z, v2.z, a2); a2 = fmaf(xv.w, v2.w, a2);
            a3 = fmaf(xv.x, v3.x, a3); a3 = fmaf(xv.y, v3.y, a3);
            a3 = fmaf(xv.z, v3.z, a3); a3 = fmaf(xv.w, v3.w, a3);
        }
        // strict < keeps first (lowest-k) minimum, matching jnp.argmin
        if (a0 < best) { best = a0; bestk = k + 0; }
        if (a1 < best) { best = a1; bestk = k + 1; }
        if (a2 < best) { best = a2; bestk = k + 2; }
        if (a3 < best) { best = a3; bestk = k + 3; }
    }

    // ---- Epilogue ----
    out[OFF_IDX + n] = (float)bestk;
    atomicAdd(&g_counts[bestk], 1.0f);

    const float4* erow = reinterpret_cast<const float4*>(ne + (size_t)bestk * EMBED_DIM);
    float* qout = out + OFF_Q + (size_t)b * (EMBED_DIM * SPATIAL) + s;
    float* dwrow = g_dw + (size_t)bestk * EMBED_DIM;

    float lsum = 0.0f;
    #pragma unroll
    for (int c4 = 0; c4 < EMBED_DIM / 4; c4++) {
        const float4 nev = erow[c4];   // -e
        const float4 xv  = x4[c4];
        // d = e - x  (reference computes quantized_cf - inputs in fp32)
        const float d0 = (-nev.x) - xv.x;
        const float d1 = (-nev.y) - xv.y;
        const float d2 = (-nev.z) - xv.z;
        const float d3 = (-nev.w) - xv.w;
        lsum = fmaf(d0, d0, lsum);
        lsum = fmaf(d1, d1, lsum);
        lsum = fmaf(d2, d2, lsum);
        lsum = fmaf(d3, d3, lsum);
        const int c = c4 * 4;
        // straight-through: out = x + (q - x), matching reference rounding
        qout[(size_t)(c + 0) * SPATIAL] = xv.x + d0;
        qout[(size_t)(c + 1) * SPATIAL] = xv.y + d1;
        qout[(size_t)(c + 2) * SPATIAL] = xv.z + d2;
        qout[(size_t)(c + 3) * SPATIAL] = xv.w + d3;
        // dw segment-sum of flat_input
        atomicAdd(&dwrow[c + 0], xv.x);
        atomicAdd(&dwrow[c + 1], xv.y);
        atomicAdd(&dwrow[c + 2], xv.z);
        atomicAdd(&dwrow[c + 3], xv.w);
    }

    // loss partial: warp reduce double, one atomic per warp
    double lacc = (double)lsum;
    #pragma unroll
    for (int off = 16; off > 0; off >>= 1)
        lacc += __shfl_down_sync(0xffffffffu, lacc, off);
    if ((threadIdx.x & 31) == 0)
        atomicAdd(&g_loss, lacc);
}

// ---------------------------------------------------------------------------
// Kernel 2: finalize — EMA update, Laplace smoothing, perplexity, loss
// ---------------------------------------------------------------------------
__global__ void __launch_bounds__(NUM_EMBED)
vq_finalize_kernel(const float* __restrict__ embed_avg,
                   const float* __restrict__ cluster_size,
                   float* __restrict__ out)
{
    __shared__ float  s_smoothed[NUM_EMBED];
    __shared__ double s_red[NUM_EMBED];

    const int t = threadIdx.x;  // 512 threads

    const float cnt = g_counts[t];
    const float ncs = cluster_size[t] * DECAY + ONE_MINUS_DECAY * cnt;
    out[OFF_CS + t] = ncs;

    // n = sum(new_cluster_size)
    s_red[t] = (double)ncs;
    __syncthreads();
    #pragma unroll
    for (int off = NUM_EMBED / 2; off > 0; off >>= 1) {
        if (t < off) s_red[t] += s_red[t + off];
        __syncthreads();
    }
    const float nf = (float)s_red[0];
    __syncthreads();

    // smoothed = n * ((ncs + alpha) / (n + K*alpha))  in fp32 like reference
    s_smoothed[t] = nf * ((ncs + LAPLACE_ALPHA) / (nf + NUM_EMBED * LAPLACE_ALPHA));

    // perplexity from empirical usage
    const float p = cnt / (float)N_TOKENS;
    s_red[t] = (double)(p * logf(p + 1e-10f));
    __syncthreads();
    #pragma unroll
    for (int off = NUM_EMBED / 2; off > 0; off >>= 1) {
        if (t < off) s_red[t] += s_red[t + off];
        __syncthreads();
    }
    if (t == 0) {
        out[OFF_PERP] = expf(-(float)s_red[0]);
        const float mean_sq = (float)(g_loss / (double)Q_ELEMS);
        out[OFF_LOSS] = COMMIT_COST * mean_sq;
    }
    __syncthreads();

    // new_embed_avg / new_embed (coalesced grid-stride)
    for (int i = t; i < NUM_EMBED * EMBED_DIM; i += NUM_EMBED) {
        const float ea = embed_avg[i] * DECAY + ONE_MINUS_DECAY * g_dw[i];
        out[OFF_EA + i]       = ea;
        out[OFF_NEWEMBED + i] = ea / s_smoothed[i >> 6];
    }
}

// ---------------------------------------------------------------------------
// Launch
// ---------------------------------------------------------------------------
extern "C" void kernel_launch(void* const* d_in, const int* in_sizes, int n_in,
                              void* d_out, int out_size)
{
    const float* inputs       = (const float*)d_in[0];
    const float* embed        = (const float*)d_in[1];
    const float* embed_avg    = (const float*)d_in[2];
    const float* cluster_size = (const float*)d_in[3];
    float* out = (float*)d_out;

    cudaFuncSetAttribute(vq_main_kernel,
                         cudaFuncAttributeMaxDynamicSharedMemorySize, SMEM_BYTES);

    vq_zero_kernel<<<(NUM_EMBED * EMBED_DIM + 255) / 256, 256>>>();
    vq_main_kernel<<<MAIN_CTAS, MAIN_THREADS, SMEM_BYTES>>>(inputs, embed, out);
    vq_finalize_kernel<<<1, NUM_EMBED>>>(embed_avg, cluster_size, out);
}

// round 4
// speedup vs baseline: 1.1688x; 1.1688x over previous
#include <cuda_runtime.h>
#include <math.h>

// Problem constants
#define NUM_EMBED   512
#define EMBED_DIM   64
#define BATCH       4
#define SPATIAL     32768           // 32*32*32
#define N_TOKENS    (BATCH*SPATIAL) // 131072
#define Q_ELEMS     (BATCH*EMBED_DIM*SPATIAL) // 8388608

// Output offsets (tuple flattened, float32)
#define OFF_LOSS      0
#define OFF_Q         1
#define OFF_PERP      (OFF_Q + Q_ELEMS)                 // 8388609
#define OFF_IDX       (OFF_PERP + 1)                    // 8388610
#define OFF_NEWEMBED  (OFF_IDX + N_TOKENS)              // 8519682
#define OFF_CS        (OFF_NEWEMBED + NUM_EMBED*EMBED_DIM) // 8552450
#define OFF_EA        (OFF_CS + NUM_EMBED)              // 8552962

#define DECAY           0.99f
#define ONE_MINUS_DECAY 0.01f
#define COMMIT_COST     0.25f
#define LAPLACE_ALPHA   1e-5f

// Scratch (device globals — no allocations allowed)
__device__ float  g_counts[NUM_EMBED];
__device__ float  g_dw[NUM_EMBED * EMBED_DIM];
__device__ double g_loss;

// ---------------------------------------------------------------------------
// Kernel 0: zero scratch (graph replays require re-zeroing every launch)
// ---------------------------------------------------------------------------
__global__ void vq_zero_kernel() {
    int i = blockIdx.x * blockDim.x + threadIdx.x;
    if (i < NUM_EMBED * EMBED_DIM) g_dw[i] = 0.0f;
    if (i < NUM_EMBED)             g_counts[i] = 0.0f;
    if (i == 0)                    g_loss = 0.0;
}

// ---------------------------------------------------------------------------
// Kernel 1: fused distance/argmin + quantized write + stats + loss partial
// Grid: 256 CTAs x 256 threads, 2 tokens per thread (tid and tid+256).
// smem: negated embed [512][64] + half-norms [512] = 133120 B  (occ = 1)
// FMA:LDS = 8:1, 8 independent accumulator chains per thread.
// ---------------------------------------------------------------------------
#define MAIN_THREADS 256
#define TOK_PER_CTA  512
#define MAIN_CTAS    (N_TOKENS / TOK_PER_CTA)   // 256
#define SMEM_BYTES   ((NUM_EMBED * EMBED_DIM + NUM_EMBED) * 4)

extern __shared__ float smem_dyn[];

__global__ void __launch_bounds__(MAIN_THREADS, 1)
vq_main_kernel(const float* __restrict__ inputs,
               const float* __restrict__ embed,
               float* __restrict__ out)
{
    float* ne    = smem_dyn;                          // -embed, [k*64 + c]
    float* halfn = smem_dyn + NUM_EMBED * EMBED_DIM;  // 0.5*||e_k||^2

    // Load negated embed into shared (coalesced float4)
    {
        const float4* src = reinterpret_cast<const float4*>(embed);
        float4* dst = reinterpret_cast<float4*>(ne);
        for (int i = threadIdx.x; i < NUM_EMBED * EMBED_DIM / 4; i += blockDim.x) {
            float4 v = src[i];
            v.x = -v.x; v.y = -v.y; v.z = -v.z; v.w = -v.w;
            dst[i] = v;
        }
    }
    __syncthreads();
    // Half norms (sequential c order)
    for (int k = threadIdx.x; k < NUM_EMBED; k += blockDim.x) {
        const float* row = ne + k * EMBED_DIM;
        float s = 0.0f;
        #pragma unroll
        for (int c = 0; c < EMBED_DIM; c++) s = fmaf(row[c], row[c], s);
        halfn[k] = 0.5f * s;
    }
    __syncthreads();

    // Two tokens for this thread: nA = base+tid, nB = base+tid+256
    const int nA = blockIdx.x * TOK_PER_CTA + threadIdx.x;
    const int nB = nA + MAIN_THREADS;
    const int bA = nA >> 15, sA = nA & (SPATIAL - 1);
    const int bB = nB >> 15, sB = nB & (SPATIAL - 1);
    const float* xinA = inputs + (size_t)bA * (EMBED_DIM * SPATIAL) + sA;
    const float* xinB = inputs + (size_t)bB * (EMBED_DIM * SPATIAL) + sB;

    // Load both token vectors into registers (coalesced per channel)
    float4 xa[EMBED_DIM / 4];
    float4 xb[EMBED_DIM / 4];
    #pragma unroll
    for (int c4 = 0; c4 < EMBED_DIM / 4; c4++) {
        xa[c4].x = xinA[(size_t)(4 * c4 + 0) * SPATIAL];
        xa[c4].y = xinA[(size_t)(4 * c4 + 1) * SPATIAL];
        xa[c4].z = xinA[(size_t)(4 * c4 + 2) * SPATIAL];
        xa[c4].w = xinA[(size_t)(4 * c4 + 3) * SPATIAL];
        xb[c4].x = xinB[(size_t)(4 * c4 + 0) * SPATIAL];
        xb[c4].y = xinB[(size_t)(4 * c4 + 1) * SPATIAL];
        xb[c4].z = xinB[(size_t)(4 * c4 + 2) * SPATIAL];
        xb[c4].w = xinB[(size_t)(4 * c4 + 3) * SPATIAL];
    }

    // Argmin over codes: h_k = 0.5||e_k||^2 - x . e_k  (ne holds -e)
    float bestA = 3.402823466e38f, bestB = 3.402823466e38f;
    int bkA = 0, bkB = 0;

    #pragma unroll 1
    for (int k = 0; k < NUM_EMBED; k += 4) {
        const float4* __restrict__ r0 = reinterpret_cast<const float4*>(ne + (size_t)(k + 0) * EMBED_DIM);
        const float4* __restrict__ r1 = reinterpret_cast<const float4*>(ne + (size_t)(k + 1) * EMBED_DIM);
        const float4* __restrict__ r2 = reinterpret_cast<const float4*>(ne + (size_t)(k + 2) * EMBED_DIM);
        const float4* __restrict__ r3 = reinterpret_cast<const float4*>(ne + (size_t)(k + 3) * EMBED_DIM);
        const float h0 = halfn[k + 0];
        const float h1 = halfn[k + 1];
        const float h2 = halfn[k + 2];
        const float h3 = halfn[k + 3];
        float a0 = h0, a1 = h1, a2 = h2, a3 = h3;   // token A
        float b0 = h0, b1 = h1, b2 = h2, b3 = h3;   // token B
        #pragma unroll
        for (int c4 = 0; c4 < EMBED_DIM / 4; c4++) {
            const float4 v0 = r0[c4];
            const float4 v1 = r1[c4];
            const float4 v2 = r2[c4];
            const float4 v3 = r3[c4];
            const float4 xA = xa[c4];
            const float4 xB = xb[c4];
            a0 = fmaf(xA.x, v0.x, a0); b0 = fmaf(xB.x, v0.x, b0);
            a1 = fmaf(xA.x, v1.x, a1); b1 = fmaf(xB.x, v1.x, b1);
            a2 = fmaf(xA.x, v2.x, a2); b2 = fmaf(xB.x, v2.x, b2);
            a3 = fmaf(xA.x, v3.x, a3); b3 = fmaf(xB.x, v3.x, b3);
            a0 = fmaf(xA.y, v0.y, a0); b0 = fmaf(xB.y, v0.y, b0);
            a1 = fmaf(xA.y, v1.y, a1); b1 = fmaf(xB.y, v1.y, b1);
            a2 = fmaf(xA.y, v2.y, a2); b2 = fmaf(xB.y, v2.y, b2);
            a3 = fmaf(xA.y, v3.y, a3); b3 = fmaf(xB.y, v3.y, b3);
            a0 = fmaf(xA.z, v0.z, a0); b0 = fmaf(xB.z, v0.z, b0);
            a1 = fmaf(xA.z, v1.z, a1); b1 = fmaf(xB.z, v1.z, b1);
            a2 = fmaf(xA.z, v2.z, a2); b2 = fmaf(xB.z, v2.z, b2);
            a3 = fmaf(xA.z, v3.z, a3); b3 = fmaf(xB.z, v3.z, b3);
            a0 = fmaf(xA.w, v0.w, a0); b0 = fmaf(xB.w, v0.w, b0);
            a1 = fmaf(xA.w, v1.w, a1); b1 = fmaf(xB.w, v1.w, b1);
            a2 = fmaf(xA.w, v2.w, a2); b2 = fmaf(xB.w, v2.w, b2);
            a3 = fmaf(xA.w, v3.w, a3); b3 = fmaf(xB.w, v3.w, b3);
        }
        // strict < keeps first (lowest-k) minimum, matching jnp.argmin
        if (a0 < bestA) { bestA = a0; bkA = k + 0; }
        if (a1 < bestA) { bestA = a1; bkA = k + 1; }
        if (a2 < bestA) { bestA = a2; bkA = k + 2; }
        if (a3 < bestA) { bestA = a3; bkA = k + 3; }
        if (b0 < bestB) { bestB = b0; bkB = k + 0; }
        if (b1 < bestB) { bestB = b1; bkB = k + 1; }
        if (b2 < bestB) { bestB = b2; bkB = k + 2; }
        if (b3 < bestB) { bestB = b3; bkB = k + 3; }
    }

    // ---- Epilogue (both tokens) ----
    out[OFF_IDX + nA] = (float)bkA;
    out[OFF_IDX + nB] = (float)bkB;
    atomicAdd(&g_counts[bkA], 1.0f);
    atomicAdd(&g_counts[bkB], 1.0f);

    const float4* erowA = reinterpret_cast<const float4*>(ne + (size_t)bkA * EMBED_DIM);
    const float4* erowB = reinterpret_cast<const float4*>(ne + (size_t)bkB * EMBED_DIM);
    float* qoutA = out + OFF_Q + (size_t)bA * (EMBED_DIM * SPATIAL) + sA;
    float* qoutB = out + OFF_Q + (size_t)bB * (EMBED_DIM * SPATIAL) + sB;
    float* dwA = g_dw + (size_t)bkA * EMBED_DIM;
    float* dwB = g_dw + (size_t)bkB * EMBED_DIM;

    float lsum = 0.0f;
    #pragma unroll
    for (int c4 = 0; c4 < EMBED_DIM / 4; c4++) {
        const float4 neA = erowA[c4];
        const float4 neB = erowB[c4];
        const float4 xA  = xa[c4];
        const float4 xB  = xb[c4];
        // d = e - x  (reference computes quantized_cf - inputs in fp32)
        const float dA0 = (-neA.x) - xA.x, dA1 = (-neA.y) - xA.y;
        const float dA2 = (-neA.z) - xA.z, dA3 = (-neA.w) - xA.w;
        const float dB0 = (-neB.x) - xB.x, dB1 = (-neB.y) - xB.y;
        const float dB2 = (-neB.z) - xB.z, dB3 = (-neB.w) - xB.w;
        lsum = fmaf(dA0, dA0, lsum); lsum = fmaf(dA1, dA1, lsum);
        lsum = fmaf(dA2, dA2, lsum); lsum = fmaf(dA3, dA3, lsum);
        lsum = fmaf(dB0, dB0, lsum); lsum = fmaf(dB1, dB1, lsum);
        lsum = fmaf(dB2, dB2, lsum); lsum = fmaf(dB3, dB3, lsum);
        const int c = c4 * 4;
        // straight-through: out = x + (q - x), matching reference rounding
        qoutA[(size_t)(c + 0) * SPATIAL] = xA.x + dA0;
        qoutA[(size_t)(c + 1) * SPATIAL] = xA.y + dA1;
        qoutA[(size_t)(c + 2) * SPATIAL] = xA.z + dA2;
        qoutA[(size_t)(c + 3) * SPATIAL] = xA.w + dA3;
        qoutB[(size_t)(c + 0) * SPATIAL] = xB.x + dB0;
        qoutB[(size_t)(c + 1) * SPATIAL] = xB.y + dB1;
        qoutB[(size_t)(c + 2) * SPATIAL] = xB.z + dB2;
        qoutB[(size_t)(c + 3) * SPATIAL] = xB.w + dB3;
        // dw segment-sum of flat_input
        atomicAdd(&dwA[c + 0], xA.x);
        atomicAdd(&dwA[c + 1], xA.y);
        atomicAdd(&dwA[c + 2], xA.z);
        atomicAdd(&dwA[c + 3], xA.w);
        atomicAdd(&dwB[c + 0], xB.x);
        atomicAdd(&dwB[c + 1], xB.y);
        atomicAdd(&dwB[c + 2], xB.z);
        atomicAdd(&dwB[c + 3], xB.w);
    }

    // loss partial: warp reduce double, one atomic per warp
    double lacc = (double)lsum;
    #pragma unroll
    for (int off = 16; off > 0; off >>= 1)
        lacc += __shfl_down_sync(0xffffffffu, lacc, off);
    if ((threadIdx.x & 31) == 0)
        atomicAdd(&g_loss, lacc);
}

// ---------------------------------------------------------------------------
// Kernel 2: finalize — EMA update, Laplace smoothing, perplexity, loss
// ---------------------------------------------------------------------------
__global__ void __launch_bounds__(NUM_EMBED)
vq_finalize_kernel(const float* __restrict__ embed_avg,
                   const float* __restrict__ cluster_size,
                   float* __restrict__ out)
{
    __shared__ float  s_smoothed[NUM_EMBED];
    __shared__ double s_red[NUM_EMBED];

    const int t = threadIdx.x;  // 512 threads

    const float cnt = g_counts[t];
    const float ncs = cluster_size[t] * DECAY + ONE_MINUS_DECAY * cnt;
    out[OFF_CS + t] = ncs;

    // n = sum(new_cluster_size)
    s_red[t] = (double)ncs;
    __syncthreads();
    #pragma unroll
    for (int off = NUM_EMBED / 2; off > 0; off >>= 1) {
        if (t < off) s_red[t] += s_red[t + off];
        __syncthreads();
    }
    const float nf = (float)s_red[0];
    __syncthreads();

    // smoothed = n * ((ncs + alpha) / (n + K*alpha))  in fp32 like reference
    s_smoothed[t] = nf * ((ncs + LAPLACE_ALPHA) / (nf + NUM_EMBED * LAPLACE_ALPHA));

    // perplexity from empirical usage
    const float p = cnt / (float)N_TOKENS;
    s_red[t] = (double)(p * logf(p + 1e-10f));
    __syncthreads();
    #pragma unroll
    for (int off = NUM_EMBED / 2; off > 0; off >>= 1) {
        if (t < off) s_red[t] += s_red[t + off];
        __syncthreads();
    }
    if (t == 0) {
        out[OFF_PERP] = expf(-(float)s_red[0]);
        const float mean_sq = (float)(g_loss / (double)Q_ELEMS);
        out[OFF_LOSS] = COMMIT_COST * mean_sq;
    }
    __syncthreads();

    // new_embed_avg / new_embed (coalesced grid-stride)
    for (int i = t; i < NUM_EMBED * EMBED_DIM; i += NUM_EMBED) {
        const float ea = embed_avg[i] * DECAY + ONE_MINUS_DECAY * g_dw[i];
        out[OFF_EA + i]       = ea;
        out[OFF_NEWEMBED + i] = ea / s_smoothed[i >> 6];
    }
}

// ---------------------------------------------------------------------------
// Launch
// ---------------------------------------------------------------------------
extern "C" void kernel_launch(void* const* d_in, const int* in_sizes, int n_in,
                              void* d_out, int out_size)
{
    const float* inputs       = (const float*)d_in[0];
    const float* embed        = (const float*)d_in[1];
    const float* embed_avg    = (const float*)d_in[2];
    const float* cluster_size = (const float*)d_in[3];
    float* out = (float*)d_out;

    cudaFuncSetAttribute(vq_main_kernel,
                         cudaFuncAttributeMaxDynamicSharedMemorySize, SMEM_BYTES);

    vq_zero_kernel<<<(NUM_EMBED * EMBED_DIM + 255) / 256, 256>>>();
    vq_main_kernel<<<MAIN_CTAS, MAIN_THREADS, SMEM_BYTES>>>(inputs, embed, out);
    vq_finalize_kernel<<<1, NUM_EMBED>>>(embed_avg, cluster_size, out);
}